// round 15
// baseline (speedup 1.0000x reference)
#include <cuda_runtime.h>
#include <cuda_fp16.h>
#include <cstdint>

// Problem constants
#define N_NODES 50000
#define N_EDGES 800000
#define N_TILES (N_EDGES / 128)     // 6250 exact
#define SCAN_BLOCKS ((N_NODES + 1023) / 1024)   // 49

// ---------------- scratch (device globals; no allocation allowed) ------------
__device__ int   g_cnt[N_NODES];
__device__ int   g_rowstart[N_NODES + 1];
__device__ int   g_wp[N_NODES];
__device__ int   g_bsum[64];
__device__ int   g_srcs[N_EDGES];          // senders sorted by receiver
__device__ int   g_rcv[N_EDGES];           // receivers sorted (run ids)
__device__ float g_A[N_NODES * 64];        // x @ W1_top + b1
__device__ float g_B[N_NODES * 64];        // x @ W1_bot
__device__ float g_accum[N_NODES * 128];   // segment sums

// ---------------- helpers -----------------------------------------------------
__device__ __forceinline__ uint32_t h2bits(__half2 h) {
    uint32_t u;
    __builtin_memcpy(&u, &h, 4);
    return u;
}
__device__ __forceinline__ void mma_fp16(float* d, const uint32_t* a,
                                         uint32_t b0, uint32_t b1) {
    asm volatile(
        "mma.sync.aligned.m16n8k16.row.col.f32.f16.f16.f32 "
        "{%0,%1,%2,%3}, {%4,%5,%6,%7}, {%8,%9}, {%0,%1,%2,%3};"
        : "+f"(d[0]), "+f"(d[1]), "+f"(d[2]), "+f"(d[3])
        : "r"(a[0]), "r"(a[1]), "r"(a[2]), "r"(a[3]), "r"(b0), "r"(b1));
}
__device__ __forceinline__ unsigned long long pk2(float lo, float hi) {
    unsigned long long r;
    asm("mov.b64 %0, {%1, %2};" : "=l"(r)
        : "r"(__float_as_uint(lo)), "r"(__float_as_uint(hi)));
    return r;
}
__device__ __forceinline__ void upk2(unsigned long long v, float& lo, float& hi) {
    unsigned int a, b;
    asm("mov.b64 {%0, %1}, %2;" : "=r"(a), "=r"(b) : "l"(v));
    lo = __uint_as_float(a);
    hi = __uint_as_float(b);
}
#define FMA2(m, a, b) \
    asm("fma.rn.f32x2 %0, %1, %2, %0;" : "+l"(m) : "l"(a), "l"(b))

// ---------------- CSR construction ------------------------------------------
// Zeros g_cnt AND g_accum (layer-1 prep) in one kernel.
__global__ void zero_kernel() {
    int i = blockIdx.x * blockDim.x + threadIdx.x;
    if (i < N_NODES) g_cnt[i] = 0;
    if (i < N_NODES * 32)
        ((float4*)g_accum)[i] = make_float4(0.f, 0.f, 0.f, 0.f);
}

__global__ void hist_kernel(const int* __restrict__ receivers) {
    int e = blockIdx.x * blockDim.x + threadIdx.x;
    if (e < N_EDGES) atomicAdd(&g_cnt[receivers[e]], 1);
}

// Multi-block scan, phase 1: per-block (1024 elems) sums.
__global__ __launch_bounds__(1024) void blocksum_kernel() {
    __shared__ int ws[32];
    int t = threadIdx.x, lane = t & 31, wid = t >> 5;
    int i = blockIdx.x * 1024 + t;
    int v = (i < N_NODES) ? g_cnt[i] : 0;
#pragma unroll
    for (int o = 16; o > 0; o >>= 1) v += __shfl_xor_sync(0xffffffffu, v, o);
    if (lane == 0) ws[wid] = v;
    __syncthreads();
    if (wid == 0) {
        int s = ws[lane];
#pragma unroll
        for (int o = 16; o > 0; o >>= 1) s += __shfl_xor_sync(0xffffffffu, s, o);
        if (lane == 0) g_bsum[blockIdx.x] = s;
    }
}

// Phase 2: tiny exclusive scan of SCAN_BLOCKS sums (serial, trivial size).
__global__ void bsum_scan_kernel() {
    if (threadIdx.x == 0) {
        int acc = 0;
        for (int b = 0; b < SCAN_BLOCKS; b++) {
            int t = g_bsum[b];
            g_bsum[b] = acc;
            acc += t;
        }
        g_rowstart[N_NODES] = acc;
    }
}

// Phase 3: per-block exclusive scan + global offset -> rowstart/wp.
__global__ __launch_bounds__(1024) void scan_out_kernel() {
    __shared__ int wsum[32];
    int t = threadIdx.x, lane = t & 31, wid = t >> 5;
    int i = blockIdx.x * 1024 + t;
    int v = (i < N_NODES) ? g_cnt[i] : 0;
    int x = v;
#pragma unroll
    for (int o = 1; o < 32; o <<= 1) {
        int y = __shfl_up_sync(0xffffffffu, x, o);
        if (lane >= o) x += y;
    }
    if (lane == 31) wsum[wid] = x;
    __syncthreads();
    if (wid == 0) {
        int s = wsum[lane];
#pragma unroll
        for (int o = 1; o < 32; o <<= 1) {
            int y = __shfl_up_sync(0xffffffffu, s, o);
            if (lane >= o) s += y;
        }
        wsum[lane] = s;
    }
    __syncthreads();
    int excl = g_bsum[blockIdx.x] + (x - v) + (wid > 0 ? wsum[wid - 1] : 0);
    if (i < N_NODES) { g_rowstart[i] = excl; g_wp[i] = excl; }
}

__global__ void fill_kernel(const int* __restrict__ senders,
                            const int* __restrict__ receivers) {
    int e = blockIdx.x * blockDim.x + threadIdx.x;
    if (e < N_EDGES) {
        int r = receivers[e];
        int pos = atomicAdd(&g_wp[r], 1);
        g_srcs[pos] = senders[e];
        g_rcv[pos] = r;
    }
}

// ---------------- per-node A/B precompute (FMA2, optional mean-on-read) ------
__global__ __launch_bounds__(128) void node_ab_kernel(
    const float* __restrict__ in, const float* __restrict__ W1,
    const float* __restrict__ b1, float* __restrict__ A, float* __restrict__ B,
    const int* __restrict__ cnt, float* __restrict__ zero_out) {
    __shared__ float xs[16][128];
    int t = threadIdx.x;
    int n0 = blockIdx.x * 16;
    {
        const float4* src = (const float4*)(in + (size_t)n0 * 128);
        float4* dst = (float4*)&xs[0][0];
#pragma unroll
        for (int i = 0; i < 4; i++) {
            int idx = t + i * 128;
            float4 v = src[idx];
            if (cnt) {
                int c = cnt[n0 + (idx >> 5)];
                float inv = (c > 0) ? 1.f / (float)c : 0.f;
                v.x *= inv; v.y *= inv; v.z *= inv; v.w *= inv;
            }
            dst[idx] = v;
        }
    }
    __syncthreads();
    if (zero_out) {
        float4* za = (float4*)(zero_out + (size_t)n0 * 128);
#pragma unroll
        for (int i = 0; i < 4; i++)
            za[t + i * 128] = make_float4(0.f, 0.f, 0.f, 0.f);
    }
    int half = t >> 6, j = t & 63;
    const float* Wb = W1 + half * (128 * 64) + j;
    unsigned long long acc2[16];
#pragma unroll
    for (int nn = 0; nn < 16; nn++) acc2[nn] = 0ull;
#pragma unroll 4
    for (int kp = 0; kp < 64; kp++) {
        float w0 = __ldg(Wb + (2 * kp) * 64);
        float w1 = __ldg(Wb + (2 * kp + 1) * 64);
        unsigned long long ww = pk2(w0, w1);
#pragma unroll
        for (int nn = 0; nn < 16; nn++) {
            unsigned long long xx =
                *(const unsigned long long*)&xs[nn][2 * kp];
            FMA2(acc2[nn], ww, xx);
        }
    }
    float binit = half ? 0.f : b1[j];
    float* out = half ? B : A;
#pragma unroll
    for (int nn = 0; nn < 16; nn++) {
        float lo, hi;
        upk2(acc2[nn], lo, hi);
        out[(size_t)(n0 + nn) * 64 + j] = lo + hi + binit;
    }
}

// ---------------- tensor-core edge kernel (fp16 m16n8k16, 8 warps) ----------
#define SM_BFRAG 0          // 2048 uint2 = 16384 B
#define SM_A     16384      // A: 128*36*4 = 18432 B; msg alias: 128*66*4 = 33792 B
#define SM_BIAS  50176      // 512 B
#define SM_RS    50688      // 129 ints = 516 B, ends 51204
#define SM_TOTAL 51456

__global__ void __launch_bounds__(256, 3) edge_mma_kernel(
    const float* __restrict__ Apre, const float* __restrict__ Bpre,
    const float* __restrict__ W2, const float* __restrict__ b2) {
    extern __shared__ char smem[];
    uint32_t* Bfrag = (uint32_t*)(smem + SM_BFRAG);
    uint32_t* As16  = (uint32_t*)(smem + SM_A);
    __half2* msgh   = (__half2*)(smem + SM_A);
    float* bias = (float*)(smem + SM_BIAS);
    int*   rs   = (int*)(smem + SM_RS);
    int tid = threadIdx.x, w = tid >> 5, lane = tid & 31;
    int wr = w >> 1, w2 = w & 1;

    for (int idx = tid; idx < 2048; idx += 256) {
        int nt = idx >> 7;
        int ks = (idx >> 5) & 3;
        int t  = idx & 31;
        int n  = nt * 8 + (t >> 2);
        int k0 = ks * 16 + 2 * (t & 3);
        __half2 p0 = __floats2half2_rn(W2[k0 * 128 + n], W2[(k0 + 1) * 128 + n]);
        __half2 p1 = __floats2half2_rn(W2[(k0 + 8) * 128 + n], W2[(k0 + 9) * 128 + n]);
        Bfrag[idx * 2 + 0] = h2bits(p0);
        Bfrag[idx * 2 + 1] = h2bits(p1);
    }
    if (tid < 128) bias[tid] = b2[tid];
    if (tid == 0) rs[128] = -1;
    __syncthreads();

    const float2* A2 = (const float2*)Apre;
    const float2* B2 = (const float2*)Bpre;
    const uint2*  Bf2 = (const uint2*)Bfrag;

    for (int tile = blockIdx.x; tile < N_TILES; tile += gridDim.x) {
        __syncthreads();   // prev tile's msg/rs fully consumed
        int e0 = tile * 128;
        int base_e = e0 + w * 16;
        int s_l = g_srcs[base_e + (lane & 15)];
        int r_l = g_rcv[base_e + (lane & 15)];
        if (lane < 16) rs[w * 16 + lane] = r_l;
#pragma unroll
        for (int jb = 0; jb < 16; jb += 8) {
            float2 va[8], vb[8];
#pragma unroll
            for (int j = 0; j < 8; j++) {
                int s = __shfl_sync(0xffffffffu, s_l, jb + j);
                int r = __shfl_sync(0xffffffffu, r_l, jb + j);
                va[j] = A2[(size_t)r * 32 + lane];
                vb[j] = B2[(size_t)s * 32 + lane];
            }
#pragma unroll
            for (int j = 0; j < 8; j++) {
                __half2 h = __floats2half2_rn(fmaxf(va[j].x + vb[j].x, 0.f),
                                              fmaxf(va[j].y + vb[j].y, 0.f));
                As16[(w * 16 + jb + j) * 36 + lane] = h2bits(h);
            }
        }
        __syncthreads();   // all rows built before cross-warp frag reads
        float d[2][8][4];
#pragma unroll
        for (int mt = 0; mt < 2; mt++)
#pragma unroll
            for (int nt = 0; nt < 8; nt++)
#pragma unroll
                for (int q = 0; q < 4; q++) d[mt][nt][q] = 0.f;
        const uint32_t* abase =
            As16 + (wr * 32 + (lane >> 2)) * 36 + (lane & 3);
        for (int ks = 0; ks < 4; ks++) {
            uint32_t a[2][4];
#pragma unroll
            for (int mt = 0; mt < 2; mt++) {
                const uint32_t* ab = abase + mt * (16 * 36) + ks * 8;
                a[mt][0] = ab[0];
                a[mt][1] = ab[8 * 36];
                a[mt][2] = ab[4];
                a[mt][3] = ab[8 * 36 + 4];
            }
            const uint2* bp = Bf2 + ks * 32 + lane;
#pragma unroll
            for (int ntl = 0; ntl < 8; ntl++) {
                uint2 bb = bp[(w2 * 8 + ntl) * 128];
                mma_fp16(d[0][ntl], a[0], bb.x, bb.y);
                mma_fp16(d[1][ntl], a[1], bb.x, bb.y);
            }
        }
        __syncthreads();   // all warps done reading As before msg overwrites
#pragma unroll
        for (int mt = 0; mt < 2; mt++) {
            int row = wr * 32 + mt * 16 + (lane >> 2);
#pragma unroll
            for (int ntl = 0; ntl < 8; ntl++) {
                int col  = (w2 * 8 + ntl) * 8 + 2 * (lane & 3);
                int colh = col >> 1;
                float2 bv = *(float2*)&bias[col];
                msgh[row * 66 + colh] = __floats2half2_rn(
                    fmaxf(d[mt][ntl][0] + bv.x, 0.f),
                    fmaxf(d[mt][ntl][1] + bv.y, 0.f));
                msgh[(row + 8) * 66 + colh] = __floats2half2_rn(
                    fmaxf(d[mt][ntl][2] + bv.x, 0.f),
                    fmaxf(d[mt][ntl][3] + bv.y, 0.f));
            }
        }
        __syncthreads();
        {
            int q = tid & 63;          // channel pair: cols 2q, 2q+1
            int seg = tid >> 6;        // 4 segments of 32 rows
            int elo = seg * 32, ehi = elo + 32;
            float2 s = make_float2(0.f, 0.f);
            int rstart = elo;
            int cur = rs[elo];
            for (int e = elo; e < ehi; e++) {
                float2 v = __half22float2(msgh[e * 66 + q]);
                s.x += v.x; s.y += v.y;
                int nxt = rs[e + 1];     // rs[128] = -1 sentinel
                bool last = (e == ehi - 1) || (nxt != cur);
                if (last) {
                    float* dst = &g_accum[(size_t)cur * 128 + 2 * q];
                    if (rstart == elo || e == ehi - 1) {
                        atomicAdd(dst, s.x);
                        atomicAdd(dst + 1, s.y);
                    } else {
                        *(float2*)dst = s;
                    }
                    s = make_float2(0.f, 0.f);
                    rstart = e + 1;
                    cur = nxt;
                }
            }
        }
    }
}

// ---------------- dense tail (mean folded in) ---------------------------------
__global__ __launch_bounds__(256) void tail_kernel(
    const float* __restrict__ h, const float* __restrict__ Wd1,
    const float* __restrict__ bd1, const float* __restrict__ Wd2,
    const float* __restrict__ bd2, float* __restrict__ out,
    const int* __restrict__ cnt) {
    __shared__ float Ws[128 * 64];
    int t = threadIdx.x;
    {
        const float4* src = (const float4*)Wd1;
        float4* dst = (float4*)Ws;
#pragma unroll
        for (int i = 0; i < 8; i++) dst[t + i * 256] = src[t + i * 256];
    }
    __syncthreads();
    int warp = t >> 5, lane = t & 31;
    int n = blockIdx.x * 8 + warp;
    if (n >= N_NODES) return;
    int c = cnt[n];
    float inv = (c > 0) ? 1.f / (float)c : 0.f;
    float x0 = h[(size_t)n * 128 + lane] * inv;
    float x1 = h[(size_t)n * 128 + 32 + lane] * inv;
    float x2 = h[(size_t)n * 128 + 64 + lane] * inv;
    float x3 = h[(size_t)n * 128 + 96 + lane] * inv;
    float g0 = bd1[lane], g1 = bd1[lane + 32];
#pragma unroll
    for (int kk = 0; kk < 32; kk++) {
        float xk;
        xk = __shfl_sync(0xffffffffu, x0, kk);
        g0 = fmaf(xk, Ws[kk * 64 + lane], g0);
        g1 = fmaf(xk, Ws[kk * 64 + lane + 32], g1);
        xk = __shfl_sync(0xffffffffu, x1, kk);
        g0 = fmaf(xk, Ws[(kk + 32) * 64 + lane], g0);
        g1 = fmaf(xk, Ws[(kk + 32) * 64 + lane + 32], g1);
        xk = __shfl_sync(0xffffffffu, x2, kk);
        g0 = fmaf(xk, Ws[(kk + 64) * 64 + lane], g0);
        g1 = fmaf(xk, Ws[(kk + 64) * 64 + lane + 32], g1);
        xk = __shfl_sync(0xffffffffu, x3, kk);
        g0 = fmaf(xk, Ws[(kk + 96) * 64 + lane], g0);
        g1 = fmaf(xk, Ws[(kk + 96) * 64 + lane + 32], g1);
    }
    g0 = fmaxf(g0, 0.f);
    g1 = fmaxf(g1, 0.f);
    float p = g0 * Wd2[lane] + g1 * Wd2[lane + 32];
#pragma unroll
    for (int o = 16; o > 0; o >>= 1) p += __shfl_xor_sync(0xffffffffu, p, o);
    if (lane == 0) out[n] = p + bd2[0];
}

// ---------------- launch ------------------------------------------------------
extern "C" void kernel_launch(void* const* d_in, const int* in_sizes, int n_in,
                              void* d_out, int out_size) {
    const float* x         = (const float*)d_in[0];
    const int*   senders   = (const int*)d_in[1];
    const int*   receivers = (const int*)d_in[2];
    const float* W1a = (const float*)d_in[3];
    const float* b1a = (const float*)d_in[4];
    const float* W2a = (const float*)d_in[5];
    const float* b2a = (const float*)d_in[6];
    const float* W1b = (const float*)d_in[7];
    const float* b1b = (const float*)d_in[8];
    const float* W2b = (const float*)d_in[9];
    const float* b2b = (const float*)d_in[10];
    const float* Wd1 = (const float*)d_in[11];
    const float* bd1 = (const float*)d_in[12];
    const float* Wd2 = (const float*)d_in[13];
    const float* bd2 = (const float*)d_in[14];
    float* out = (float*)d_out;

    static float* pA = nullptr;
    static float* pB = nullptr;
    static float* pAcc = nullptr;
    static int*   pCnt = nullptr;
    static int    nSM = 148;
    static cudaStream_t s2 = nullptr;
    static cudaEvent_t evFork = nullptr, evJoin = nullptr;
    if (!pA) {
        cudaGetSymbolAddress((void**)&pA, g_A);
        cudaGetSymbolAddress((void**)&pB, g_B);
        cudaGetSymbolAddress((void**)&pAcc, g_accum);
        cudaGetSymbolAddress((void**)&pCnt, g_cnt);
        cudaFuncSetAttribute(edge_mma_kernel,
                             cudaFuncAttributeMaxDynamicSharedMemorySize,
                             SM_TOTAL);
        cudaDeviceProp prop;
        if (cudaGetDeviceProperties(&prop, 0) == cudaSuccess)
            nSM = prop.multiProcessorCount;
        cudaStreamCreateWithFlags(&s2, cudaStreamNonBlocking);
        cudaEventCreateWithFlags(&evFork, cudaEventDisableTiming);
        cudaEventCreateWithFlags(&evJoin, cudaEventDisableTiming);
    }

    // Fork: node_ab(L1) on side stream, concurrent with CSR build on main.
    cudaEventRecord(evFork, 0);
    cudaStreamWaitEvent(s2, evFork, 0);
    node_ab_kernel<<<N_NODES / 16, 128, 0, s2>>>(x, W1a, b1a, pA, pB,
                                                 nullptr, nullptr);
    cudaEventRecord(evJoin, s2);

    // Main stream: CSR build (zero_kernel also zeroes accum for layer 1)
    zero_kernel<<<(N_NODES * 32 + 255) / 256, 256>>>();
    hist_kernel<<<(N_EDGES + 255) / 256, 256>>>(receivers);
    blocksum_kernel<<<SCAN_BLOCKS, 1024>>>();
    bsum_scan_kernel<<<1, 32>>>();
    scan_out_kernel<<<SCAN_BLOCKS, 1024>>>();
    fill_kernel<<<(N_EDGES + 255) / 256, 256>>>(senders, receivers);

    // Join before edge layer 1 (needs g_A/g_B from side stream).
    cudaStreamWaitEvent(0, evJoin, 0);

    int mmaBlocks = 3 * nSM;

    // Layer 1
    edge_mma_kernel<<<mmaBlocks, 256, SM_TOTAL>>>(pA, pB, W2a, b2a);
    // Layer 2 (mean folded into the accum read; accum re-zeroed in-kernel)
    node_ab_kernel<<<N_NODES / 16, 128>>>(pAcc, W1b, b1b, pA, pB, pCnt, pAcc);
    edge_mma_kernel<<<mmaBlocks, 256, SM_TOTAL>>>(pA, pB, W2b, b2b);
    // Dense tail (mean of layer-2 folded in)
    tail_kernel<<<(N_NODES + 7) / 8, 256>>>(pAcc, Wd1, bd1, Wd2, bd2, out, pCnt);
}

// round 16
// speedup vs baseline: 1.5148x; 1.5148x over previous
#include <cuda_runtime.h>
#include <cuda_fp16.h>
#include <cstdint>

// Problem constants
#define N_NODES 50000
#define N_EDGES 800000
#define N_TILES (N_EDGES / 128)     // 6250 exact
#define SCAN_BLOCKS ((N_NODES + 1023) / 1024)   // 49

// ---------------- scratch (device globals; no allocation allowed) ------------
__device__ int   g_cnt[N_NODES];
__device__ int   g_rowstart[N_NODES + 1];
__device__ int   g_wp[N_NODES];
__device__ int   g_bsum[64];
__device__ int   g_srcs[N_EDGES];          // senders sorted by receiver
__device__ int   g_rcv[N_EDGES];           // receivers sorted (run ids)
__device__ float g_A[N_NODES * 64];        // x @ W1_top + b1
__device__ float g_B[N_NODES * 64];        // x @ W1_bot
__device__ float g_accum[N_NODES * 128];   // segment sums

// ---------------- helpers -----------------------------------------------------
__device__ __forceinline__ uint32_t h2bits(__half2 h) {
    uint32_t u;
    __builtin_memcpy(&u, &h, 4);
    return u;
}
__device__ __forceinline__ void mma_fp16(float* d, const uint32_t* a,
                                         uint32_t b0, uint32_t b1) {
    asm volatile(
        "mma.sync.aligned.m16n8k16.row.col.f32.f16.f16.f32 "
        "{%0,%1,%2,%3}, {%4,%5,%6,%7}, {%8,%9}, {%0,%1,%2,%3};"
        : "+f"(d[0]), "+f"(d[1]), "+f"(d[2]), "+f"(d[3])
        : "r"(a[0]), "r"(a[1]), "r"(a[2]), "r"(a[3]), "r"(b0), "r"(b1));
}
__device__ __forceinline__ unsigned long long pk2(float lo, float hi) {
    unsigned long long r;
    asm("mov.b64 %0, {%1, %2};" : "=l"(r)
        : "r"(__float_as_uint(lo)), "r"(__float_as_uint(hi)));
    return r;
}
__device__ __forceinline__ void upk2(unsigned long long v, float& lo, float& hi) {
    unsigned int a, b;
    asm("mov.b64 {%0, %1}, %2;" : "=r"(a), "=r"(b) : "l"(v));
    lo = __uint_as_float(a);
    hi = __uint_as_float(b);
}
#define FMA2(m, a, b) \
    asm("fma.rn.f32x2 %0, %1, %2, %0;" : "+l"(m) : "l"(a), "l"(b))

// ---------------- CSR construction ------------------------------------------
// Zeros g_cnt AND g_accum (layer-1 prep) in one kernel.
__global__ void zero_kernel() {
    int i = blockIdx.x * blockDim.x + threadIdx.x;
    if (i < N_NODES) g_cnt[i] = 0;
    if (i < N_NODES * 32)
        ((float4*)g_accum)[i] = make_float4(0.f, 0.f, 0.f, 0.f);
}

__global__ void hist_kernel(const int* __restrict__ receivers) {
    int e = blockIdx.x * blockDim.x + threadIdx.x;
    if (e < N_EDGES) atomicAdd(&g_cnt[receivers[e]], 1);
}

// Multi-block scan, phase 1: per-block (1024 elems) sums.
__global__ __launch_bounds__(1024) void blocksum_kernel() {
    __shared__ int ws[32];
    int t = threadIdx.x, lane = t & 31, wid = t >> 5;
    int i = blockIdx.x * 1024 + t;
    int v = (i < N_NODES) ? g_cnt[i] : 0;
#pragma unroll
    for (int o = 16; o > 0; o >>= 1) v += __shfl_xor_sync(0xffffffffu, v, o);
    if (lane == 0) ws[wid] = v;
    __syncthreads();
    if (wid == 0) {
        int s = ws[lane];
#pragma unroll
        for (int o = 16; o > 0; o >>= 1) s += __shfl_xor_sync(0xffffffffu, s, o);
        if (lane == 0) g_bsum[blockIdx.x] = s;
    }
}

// Phase 2: tiny exclusive scan of SCAN_BLOCKS sums (serial, trivial size).
__global__ void bsum_scan_kernel() {
    if (threadIdx.x == 0) {
        int acc = 0;
        for (int b = 0; b < SCAN_BLOCKS; b++) {
            int t = g_bsum[b];
            g_bsum[b] = acc;
            acc += t;
        }
        g_rowstart[N_NODES] = acc;
    }
}

// Phase 3: per-block exclusive scan + global offset -> rowstart/wp.
__global__ __launch_bounds__(1024) void scan_out_kernel() {
    __shared__ int wsum[32];
    int t = threadIdx.x, lane = t & 31, wid = t >> 5;
    int i = blockIdx.x * 1024 + t;
    int v = (i < N_NODES) ? g_cnt[i] : 0;
    int x = v;
#pragma unroll
    for (int o = 1; o < 32; o <<= 1) {
        int y = __shfl_up_sync(0xffffffffu, x, o);
        if (lane >= o) x += y;
    }
    if (lane == 31) wsum[wid] = x;
    __syncthreads();
    if (wid == 0) {
        int s = wsum[lane];
#pragma unroll
        for (int o = 1; o < 32; o <<= 1) {
            int y = __shfl_up_sync(0xffffffffu, s, o);
            if (lane >= o) s += y;
        }
        wsum[lane] = s;
    }
    __syncthreads();
    int excl = g_bsum[blockIdx.x] + (x - v) + (wid > 0 ? wsum[wid - 1] : 0);
    if (i < N_NODES) { g_rowstart[i] = excl; g_wp[i] = excl; }
}

__global__ void fill_kernel(const int* __restrict__ senders,
                            const int* __restrict__ receivers) {
    int e = blockIdx.x * blockDim.x + threadIdx.x;
    if (e < N_EDGES) {
        int r = receivers[e];
        int pos = atomicAdd(&g_wp[r], 1);
        g_srcs[pos] = senders[e];
        g_rcv[pos] = r;
    }
}

// ---------------- per-node A/B precompute (FMA2, optional mean-on-read) ------
__global__ __launch_bounds__(128) void node_ab_kernel(
    const float* __restrict__ in, const float* __restrict__ W1,
    const float* __restrict__ b1, float* __restrict__ A, float* __restrict__ B,
    const int* __restrict__ cnt, float* __restrict__ zero_out) {
    __shared__ float xs[16][128];
    int t = threadIdx.x;
    int n0 = blockIdx.x * 16;
    {
        const float4* src = (const float4*)(in + (size_t)n0 * 128);
        float4* dst = (float4*)&xs[0][0];
#pragma unroll
        for (int i = 0; i < 4; i++) {
            int idx = t + i * 128;
            float4 v = src[idx];
            if (cnt) {
                int c = cnt[n0 + (idx >> 5)];
                float inv = (c > 0) ? 1.f / (float)c : 0.f;
                v.x *= inv; v.y *= inv; v.z *= inv; v.w *= inv;
            }
            dst[idx] = v;
        }
    }
    __syncthreads();
    if (zero_out) {
        float4* za = (float4*)(zero_out + (size_t)n0 * 128);
#pragma unroll
        for (int i = 0; i < 4; i++)
            za[t + i * 128] = make_float4(0.f, 0.f, 0.f, 0.f);
    }
    int half = t >> 6, j = t & 63;
    const float* Wb = W1 + half * (128 * 64) + j;
    unsigned long long acc2[16];
#pragma unroll
    for (int nn = 0; nn < 16; nn++) acc2[nn] = 0ull;
#pragma unroll 4
    for (int kp = 0; kp < 64; kp++) {
        float w0 = __ldg(Wb + (2 * kp) * 64);
        float w1 = __ldg(Wb + (2 * kp + 1) * 64);
        unsigned long long ww = pk2(w0, w1);
#pragma unroll
        for (int nn = 0; nn < 16; nn++) {
            unsigned long long xx =
                *(const unsigned long long*)&xs[nn][2 * kp];
            FMA2(acc2[nn], ww, xx);
        }
    }
    float binit = half ? 0.f : b1[j];
    float* out = half ? B : A;
#pragma unroll
    for (int nn = 0; nn < 16; nn++) {
        float lo, hi;
        upk2(acc2[nn], lo, hi);
        out[(size_t)(n0 + nn) * 64 + j] = lo + hi + binit;
    }
}

// ---------------- tensor-core edge kernel (fp16 m16n8k16, 8 warps) ----------
#define SM_BFRAG 0          // 2048 uint2 = 16384 B
#define SM_A     16384      // A: 128*36*4 = 18432 B; msg alias: 128*66*4 = 33792 B
#define SM_BIAS  50176      // 512 B
#define SM_RS    50688      // 129 ints = 516 B, ends 51204
#define SM_TOTAL 51456

__global__ void __launch_bounds__(256, 3) edge_mma_kernel(
    const float* __restrict__ Apre, const float* __restrict__ Bpre,
    const float* __restrict__ W2, const float* __restrict__ b2) {
    extern __shared__ char smem[];
    uint32_t* Bfrag = (uint32_t*)(smem + SM_BFRAG);
    uint32_t* As16  = (uint32_t*)(smem + SM_A);
    __half2* msgh   = (__half2*)(smem + SM_A);
    float* bias = (float*)(smem + SM_BIAS);
    int*   rs   = (int*)(smem + SM_RS);
    int tid = threadIdx.x, w = tid >> 5, lane = tid & 31;
    int wr = w >> 1, w2 = w & 1;

    for (int idx = tid; idx < 2048; idx += 256) {
        int nt = idx >> 7;
        int ks = (idx >> 5) & 3;
        int t  = idx & 31;
        int n  = nt * 8 + (t >> 2);
        int k0 = ks * 16 + 2 * (t & 3);
        __half2 p0 = __floats2half2_rn(W2[k0 * 128 + n], W2[(k0 + 1) * 128 + n]);
        __half2 p1 = __floats2half2_rn(W2[(k0 + 8) * 128 + n], W2[(k0 + 9) * 128 + n]);
        Bfrag[idx * 2 + 0] = h2bits(p0);
        Bfrag[idx * 2 + 1] = h2bits(p1);
    }
    if (tid < 128) bias[tid] = b2[tid];
    if (tid == 0) rs[128] = -1;
    __syncthreads();

    const float2* A2 = (const float2*)Apre;
    const float2* B2 = (const float2*)Bpre;
    const uint2*  Bf2 = (const uint2*)Bfrag;

    for (int tile = blockIdx.x; tile < N_TILES; tile += gridDim.x) {
        __syncthreads();   // prev tile's msg/rs fully consumed
        int e0 = tile * 128;
        int base_e = e0 + w * 16;
        int s_l = g_srcs[base_e + (lane & 15)];
        int r_l = g_rcv[base_e + (lane & 15)];
        if (lane < 16) rs[w * 16 + lane] = r_l;
#pragma unroll
        for (int jb = 0; jb < 16; jb += 8) {
            float2 va[8], vb[8];
#pragma unroll
            for (int j = 0; j < 8; j++) {
                int s = __shfl_sync(0xffffffffu, s_l, jb + j);
                int r = __shfl_sync(0xffffffffu, r_l, jb + j);
                va[j] = A2[(size_t)r * 32 + lane];
                vb[j] = B2[(size_t)s * 32 + lane];
            }
#pragma unroll
            for (int j = 0; j < 8; j++) {
                __half2 h = __floats2half2_rn(fmaxf(va[j].x + vb[j].x, 0.f),
                                              fmaxf(va[j].y + vb[j].y, 0.f));
                As16[(w * 16 + jb + j) * 36 + lane] = h2bits(h);
            }
        }
        __syncthreads();   // all rows built before cross-warp frag reads
        float d[2][8][4];
#pragma unroll
        for (int mt = 0; mt < 2; mt++)
#pragma unroll
            for (int nt = 0; nt < 8; nt++)
#pragma unroll
                for (int q = 0; q < 4; q++) d[mt][nt][q] = 0.f;
        const uint32_t* abase =
            As16 + (wr * 32 + (lane >> 2)) * 36 + (lane & 3);
        for (int ks = 0; ks < 4; ks++) {
            uint32_t a[2][4];
#pragma unroll
            for (int mt = 0; mt < 2; mt++) {
                const uint32_t* ab = abase + mt * (16 * 36) + ks * 8;
                a[mt][0] = ab[0];
                a[mt][1] = ab[8 * 36];
                a[mt][2] = ab[4];
                a[mt][3] = ab[8 * 36 + 4];
            }
            const uint2* bp = Bf2 + ks * 32 + lane;
#pragma unroll
            for (int ntl = 0; ntl < 8; ntl++) {
                uint2 bb = bp[(w2 * 8 + ntl) * 128];
                mma_fp16(d[0][ntl], a[0], bb.x, bb.y);
                mma_fp16(d[1][ntl], a[1], bb.x, bb.y);
            }
        }
        __syncthreads();   // all warps done reading As before msg overwrites
#pragma unroll
        for (int mt = 0; mt < 2; mt++) {
            int row = wr * 32 + mt * 16 + (lane >> 2);
#pragma unroll
            for (int ntl = 0; ntl < 8; ntl++) {
                int col  = (w2 * 8 + ntl) * 8 + 2 * (lane & 3);
                int colh = col >> 1;
                float2 bv = *(float2*)&bias[col];
                msgh[row * 66 + colh] = __floats2half2_rn(
                    fmaxf(d[mt][ntl][0] + bv.x, 0.f),
                    fmaxf(d[mt][ntl][1] + bv.y, 0.f));
                msgh[(row + 8) * 66 + colh] = __floats2half2_rn(
                    fmaxf(d[mt][ntl][2] + bv.x, 0.f),
                    fmaxf(d[mt][ntl][3] + bv.y, 0.f));
            }
        }
        __syncthreads();
        {
            int q = tid & 63;          // channel pair: cols 2q, 2q+1
            int seg = tid >> 6;        // 4 segments of 32 rows
            int elo = seg * 32, ehi = elo + 32;
            float2 s = make_float2(0.f, 0.f);
            int rstart = elo;
            int cur = rs[elo];
            for (int e = elo; e < ehi; e++) {
                float2 v = __half22float2(msgh[e * 66 + q]);
                s.x += v.x; s.y += v.y;
                int nxt = rs[e + 1];     // rs[128] = -1 sentinel
                bool last = (e == ehi - 1) || (nxt != cur);
                if (last) {
                    float* dst = &g_accum[(size_t)cur * 128 + 2 * q];
                    if (rstart == elo || e == ehi - 1) {
                        atomicAdd(dst, s.x);
                        atomicAdd(dst + 1, s.y);
                    } else {
                        *(float2*)dst = s;
                    }
                    s = make_float2(0.f, 0.f);
                    rstart = e + 1;
                    cur = nxt;
                }
            }
        }
    }
}

// ---------------- dense tail (mean folded in) ---------------------------------
__global__ __launch_bounds__(256) void tail_kernel(
    const float* __restrict__ h, const float* __restrict__ Wd1,
    const float* __restrict__ bd1, const float* __restrict__ Wd2,
    const float* __restrict__ bd2, float* __restrict__ out,
    const int* __restrict__ cnt) {
    __shared__ float Ws[128 * 64];
    int t = threadIdx.x;
    {
        const float4* src = (const float4*)Wd1;
        float4* dst = (float4*)Ws;
#pragma unroll
        for (int i = 0; i < 8; i++) dst[t + i * 256] = src[t + i * 256];
    }
    __syncthreads();
    int warp = t >> 5, lane = t & 31;
    int n = blockIdx.x * 8 + warp;
    if (n >= N_NODES) return;
    int c = cnt[n];
    float inv = (c > 0) ? 1.f / (float)c : 0.f;
    float x0 = h[(size_t)n * 128 + lane] * inv;
    float x1 = h[(size_t)n * 128 + 32 + lane] * inv;
    float x2 = h[(size_t)n * 128 + 64 + lane] * inv;
    float x3 = h[(size_t)n * 128 + 96 + lane] * inv;
    float g0 = bd1[lane], g1 = bd1[lane + 32];
#pragma unroll
    for (int kk = 0; kk < 32; kk++) {
        float xk;
        xk = __shfl_sync(0xffffffffu, x0, kk);
        g0 = fmaf(xk, Ws[kk * 64 + lane], g0);
        g1 = fmaf(xk, Ws[kk * 64 + lane + 32], g1);
        xk = __shfl_sync(0xffffffffu, x1, kk);
        g0 = fmaf(xk, Ws[(kk + 32) * 64 + lane], g0);
        g1 = fmaf(xk, Ws[(kk + 32) * 64 + lane + 32], g1);
        xk = __shfl_sync(0xffffffffu, x2, kk);
        g0 = fmaf(xk, Ws[(kk + 64) * 64 + lane], g0);
        g1 = fmaf(xk, Ws[(kk + 64) * 64 + lane + 32], g1);
        xk = __shfl_sync(0xffffffffu, x3, kk);
        g0 = fmaf(xk, Ws[(kk + 96) * 64 + lane], g0);
        g1 = fmaf(xk, Ws[(kk + 96) * 64 + lane + 32], g1);
    }
    g0 = fmaxf(g0, 0.f);
    g1 = fmaxf(g1, 0.f);
    float p = g0 * Wd2[lane] + g1 * Wd2[lane + 32];
#pragma unroll
    for (int o = 16; o > 0; o >>= 1) p += __shfl_xor_sync(0xffffffffu, p, o);
    if (lane == 0) out[n] = p + bd2[0];
}

// ---------------- launch ------------------------------------------------------
extern "C" void kernel_launch(void* const* d_in, const int* in_sizes, int n_in,
                              void* d_out, int out_size) {
    const float* x         = (const float*)d_in[0];
    const int*   senders   = (const int*)d_in[1];
    const int*   receivers = (const int*)d_in[2];
    const float* W1a = (const float*)d_in[3];
    const float* b1a = (const float*)d_in[4];
    const float* W2a = (const float*)d_in[5];
    const float* b2a = (const float*)d_in[6];
    const float* W1b = (const float*)d_in[7];
    const float* b1b = (const float*)d_in[8];
    const float* W2b = (const float*)d_in[9];
    const float* b2b = (const float*)d_in[10];
    const float* Wd1 = (const float*)d_in[11];
    const float* bd1 = (const float*)d_in[12];
    const float* Wd2 = (const float*)d_in[13];
    const float* bd2 = (const float*)d_in[14];
    float* out = (float*)d_out;

    static float* pA = nullptr;
    static float* pB = nullptr;
    static float* pAcc = nullptr;
    static int*   pCnt = nullptr;
    static int    nSM = 148;
    if (!pA) {
        cudaGetSymbolAddress((void**)&pA, g_A);
        cudaGetSymbolAddress((void**)&pB, g_B);
        cudaGetSymbolAddress((void**)&pAcc, g_accum);
        cudaGetSymbolAddress((void**)&pCnt, g_cnt);
        cudaFuncSetAttribute(edge_mma_kernel,
                             cudaFuncAttributeMaxDynamicSharedMemorySize,
                             SM_TOTAL);
        cudaDeviceProp prop;
        if (cudaGetDeviceProperties(&prop, 0) == cudaSuccess)
            nSM = prop.multiProcessorCount;
    }

    // Single linear stream — R15 showed cross-stream fork/join in the captured
    // graph costs ~190 us on this harness. node_ab(L1) first, then CSR chain.
    node_ab_kernel<<<N_NODES / 16, 128>>>(x, W1a, b1a, pA, pB, nullptr, nullptr);
    zero_kernel<<<(N_NODES * 32 + 255) / 256, 256>>>();
    hist_kernel<<<(N_EDGES + 255) / 256, 256>>>(receivers);
    blocksum_kernel<<<SCAN_BLOCKS, 1024>>>();
    bsum_scan_kernel<<<1, 32>>>();
    scan_out_kernel<<<SCAN_BLOCKS, 1024>>>();
    fill_kernel<<<(N_EDGES + 255) / 256, 256>>>(senders, receivers);

    int mmaBlocks = 3 * nSM;

    // Layer 1
    edge_mma_kernel<<<mmaBlocks, 256, SM_TOTAL>>>(pA, pB, W2a, b2a);
    // Layer 2 (mean folded into the accum read; accum re-zeroed in-kernel)
    node_ab_kernel<<<N_NODES / 16, 128>>>(pAcc, W1b, b1b, pA, pB, pCnt, pAcc);
    edge_mma_kernel<<<mmaBlocks, 256, SM_TOTAL>>>(pA, pB, W2b, b2b);
    // Dense tail (mean of layer-2 folded in)
    tail_kernel<<<(N_NODES + 7) / 8, 256>>>(pAcc, Wd1, bd1, Wd2, bd2, out, pCnt);
}

// round 17
// speedup vs baseline: 1.5162x; 1.0010x over previous
#include <cuda_runtime.h>
#include <cuda_fp16.h>
#include <cstdint>

// Problem constants
#define N_NODES 50000
#define N_EDGES 800000
#define N_PTILES (N_EDGES / 32)     // 25000 exact (32-edge pair tiles)
#define SCAN_BLOCKS ((N_NODES + 1023) / 1024)   // 49

// ---------------- scratch (device globals; no allocation allowed) ------------
__device__ int   g_cnt[N_NODES];
__device__ int   g_rowstart[N_NODES + 1];
__device__ int   g_wp[N_NODES];
__device__ int   g_bsum[64];
__device__ int   g_srcs[N_EDGES];          // senders sorted by receiver
__device__ int   g_rcv[N_EDGES];           // receivers sorted (run ids)
__device__ float g_A[N_NODES * 64];        // x @ W1_top + b1
__device__ float g_B[N_NODES * 64];        // x @ W1_bot
__device__ float g_accum[N_NODES * 128];   // segment sums

// ---------------- helpers -----------------------------------------------------
__device__ __forceinline__ uint32_t h2bits(__half2 h) {
    uint32_t u;
    __builtin_memcpy(&u, &h, 4);
    return u;
}
__device__ __forceinline__ void mma_fp16(float* d, const uint32_t* a,
                                         uint32_t b0, uint32_t b1) {
    asm volatile(
        "mma.sync.aligned.m16n8k16.row.col.f32.f16.f16.f32 "
        "{%0,%1,%2,%3}, {%4,%5,%6,%7}, {%8,%9}, {%0,%1,%2,%3};"
        : "+f"(d[0]), "+f"(d[1]), "+f"(d[2]), "+f"(d[3])
        : "r"(a[0]), "r"(a[1]), "r"(a[2]), "r"(a[3]), "r"(b0), "r"(b1));
}
__device__ __forceinline__ unsigned long long pk2(float lo, float hi) {
    unsigned long long r;
    asm("mov.b64 %0, {%1, %2};" : "=l"(r)
        : "r"(__float_as_uint(lo)), "r"(__float_as_uint(hi)));
    return r;
}
__device__ __forceinline__ void upk2(unsigned long long v, float& lo, float& hi) {
    unsigned int a, b;
    asm("mov.b64 {%0, %1}, %2;" : "=r"(a), "=r"(b) : "l"(v));
    lo = __uint_as_float(a);
    hi = __uint_as_float(b);
}
#define FMA2(m, a, b) \
    asm("fma.rn.f32x2 %0, %1, %2, %0;" : "+l"(m) : "l"(a), "l"(b))
// Named pair barrier: 64 threads (one warp pair), id = pair+1.
#define PBAR(pr) asm volatile("bar.sync %0, 64;" :: "r"((pr) + 1) : "memory")

// ---------------- CSR construction ------------------------------------------
// Zeros g_cnt AND g_accum (layer-1 prep) in one kernel.
__global__ void zero_kernel() {
    int i = blockIdx.x * blockDim.x + threadIdx.x;
    if (i < N_NODES) g_cnt[i] = 0;
    if (i < N_NODES * 32)
        ((float4*)g_accum)[i] = make_float4(0.f, 0.f, 0.f, 0.f);
}

__global__ void hist_kernel(const int* __restrict__ receivers) {
    int e = blockIdx.x * blockDim.x + threadIdx.x;
    if (e < N_EDGES) atomicAdd(&g_cnt[receivers[e]], 1);
}

// Multi-block scan, phase 1: per-block (1024 elems) sums.
__global__ __launch_bounds__(1024) void blocksum_kernel() {
    __shared__ int ws[32];
    int t = threadIdx.x, lane = t & 31, wid = t >> 5;
    int i = blockIdx.x * 1024 + t;
    int v = (i < N_NODES) ? g_cnt[i] : 0;
#pragma unroll
    for (int o = 16; o > 0; o >>= 1) v += __shfl_xor_sync(0xffffffffu, v, o);
    if (lane == 0) ws[wid] = v;
    __syncthreads();
    if (wid == 0) {
        int s = ws[lane];
#pragma unroll
        for (int o = 16; o > 0; o >>= 1) s += __shfl_xor_sync(0xffffffffu, s, o);
        if (lane == 0) g_bsum[blockIdx.x] = s;
    }
}

// Phase 2: tiny exclusive scan of SCAN_BLOCKS sums.
__global__ void bsum_scan_kernel() {
    if (threadIdx.x == 0) {
        int acc = 0;
        for (int b = 0; b < SCAN_BLOCKS; b++) {
            int t = g_bsum[b];
            g_bsum[b] = acc;
            acc += t;
        }
        g_rowstart[N_NODES] = acc;
    }
}

// Phase 3: per-block exclusive scan + global offset -> rowstart/wp.
__global__ __launch_bounds__(1024) void scan_out_kernel() {
    __shared__ int wsum[32];
    int t = threadIdx.x, lane = t & 31, wid = t >> 5;
    int i = blockIdx.x * 1024 + t;
    int v = (i < N_NODES) ? g_cnt[i] : 0;
    int x = v;
#pragma unroll
    for (int o = 1; o < 32; o <<= 1) {
        int y = __shfl_up_sync(0xffffffffu, x, o);
        if (lane >= o) x += y;
    }
    if (lane == 31) wsum[wid] = x;
    __syncthreads();
    if (wid == 0) {
        int s = wsum[lane];
#pragma unroll
        for (int o = 1; o < 32; o <<= 1) {
            int y = __shfl_up_sync(0xffffffffu, s, o);
            if (lane >= o) s += y;
        }
        wsum[lane] = s;
    }
    __syncthreads();
    int excl = g_bsum[blockIdx.x] + (x - v) + (wid > 0 ? wsum[wid - 1] : 0);
    if (i < N_NODES) { g_rowstart[i] = excl; g_wp[i] = excl; }
}

__global__ void fill_kernel(const int* __restrict__ senders,
                            const int* __restrict__ receivers) {
    int e = blockIdx.x * blockDim.x + threadIdx.x;
    if (e < N_EDGES) {
        int r = receivers[e];
        int pos = atomicAdd(&g_wp[r], 1);
        g_srcs[pos] = senders[e];
        g_rcv[pos] = r;
    }
}

// ---------------- per-node A/B precompute (FMA2, optional mean-on-read) ------
__global__ __launch_bounds__(128) void node_ab_kernel(
    const float* __restrict__ in, const float* __restrict__ W1,
    const float* __restrict__ b1, float* __restrict__ A, float* __restrict__ B,
    const int* __restrict__ cnt, float* __restrict__ zero_out) {
    __shared__ float xs[16][128];
    int t = threadIdx.x;
    int n0 = blockIdx.x * 16;
    {
        const float4* src = (const float4*)(in + (size_t)n0 * 128);
        float4* dst = (float4*)&xs[0][0];
#pragma unroll
        for (int i = 0; i < 4; i++) {
            int idx = t + i * 128;
            float4 v = src[idx];
            if (cnt) {
                int c = cnt[n0 + (idx >> 5)];
                float inv = (c > 0) ? 1.f / (float)c : 0.f;
                v.x *= inv; v.y *= inv; v.z *= inv; v.w *= inv;
            }
            dst[idx] = v;
        }
    }
    __syncthreads();
    if (zero_out) {
        float4* za = (float4*)(zero_out + (size_t)n0 * 128);
#pragma unroll
        for (int i = 0; i < 4; i++)
            za[t + i * 128] = make_float4(0.f, 0.f, 0.f, 0.f);
    }
    int half = t >> 6, j = t & 63;
    const float* Wb = W1 + half * (128 * 64) + j;
    unsigned long long acc2[16];
#pragma unroll
    for (int nn = 0; nn < 16; nn++) acc2[nn] = 0ull;
#pragma unroll 4
    for (int kp = 0; kp < 64; kp++) {
        float w0 = __ldg(Wb + (2 * kp) * 64);
        float w1 = __ldg(Wb + (2 * kp + 1) * 64);
        unsigned long long ww = pk2(w0, w1);
#pragma unroll
        for (int nn = 0; nn < 16; nn++) {
            unsigned long long xx =
                *(const unsigned long long*)&xs[nn][2 * kp];
            FMA2(acc2[nn], ww, xx);
        }
    }
    float binit = half ? 0.f : b1[j];
    float* out = half ? B : A;
#pragma unroll
    for (int nn = 0; nn < 16; nn++) {
        float lo, hi;
        upk2(acc2[nn], lo, hi);
        out[(size_t)(n0 + nn) * 64 + j] = lo + hi + binit;
    }
}

// ---------------- tensor-core edge kernel (fp16 m16n8k16, pair-decoupled) ---
// Block = 8 warps = 4 INDEPENDENT warp pairs. Pair pr owns 32-edge tiles
// (tile = blockIdx.x*4 + pr, stride gridDim.x*4), a private 8448 B scratch
// (As rows stride 36 u32, aliased by msg rows stride 66 half2), and private
// rs[33] (sentinel at [32]). All tile-loop syncs are named pair barriers
// (bar.sync pr+1, 64) — no block-wide convoys. Per-edge work identical to
// the R16 kernel: warp w2 of the pair computes rows 32 x cols [64*w2,+64).
#define SM_BFRAG 0          // 2048 uint2 = 16384 B
#define SM_A     16384      // 4 pair regions * 8448 B = 33792 B
#define SM_BIAS  50176      // 512 B
#define SM_RS    50688      // 4 * 33 ints = 528 B, ends 51216
#define SM_TOTAL 51456
#define PAIR_SCRATCH_U32 2112   // 8448 B / 4

__global__ void __launch_bounds__(256, 3) edge_mma_kernel(
    const float* __restrict__ Apre, const float* __restrict__ Bpre,
    const float* __restrict__ W2, const float* __restrict__ b2) {
    extern __shared__ char smem[];
    uint32_t* Bfrag = (uint32_t*)(smem + SM_BFRAG);
    float* bias = (float*)(smem + SM_BIAS);
    int*   rs   = (int*)(smem + SM_RS);
    int tid = threadIdx.x, w = tid >> 5, lane = tid & 31;
    int pr = w >> 1, w2 = w & 1;
    uint32_t* As16 = (uint32_t*)(smem + SM_A) + pr * PAIR_SCRATCH_U32;
    __half2*  msgh = (__half2*)As16;          // alias, row stride 66
    int* prs = rs + pr * 33;

    // Pack W2 (K=64 x N=128) into fp16 fragment order (block-wide, once).
    for (int idx = tid; idx < 2048; idx += 256) {
        int nt = idx >> 7;
        int ks = (idx >> 5) & 3;
        int t  = idx & 31;
        int n  = nt * 8 + (t >> 2);
        int k0 = ks * 16 + 2 * (t & 3);
        __half2 p0 = __floats2half2_rn(W2[k0 * 128 + n], W2[(k0 + 1) * 128 + n]);
        __half2 p1 = __floats2half2_rn(W2[(k0 + 8) * 128 + n], W2[(k0 + 9) * 128 + n]);
        Bfrag[idx * 2 + 0] = h2bits(p0);
        Bfrag[idx * 2 + 1] = h2bits(p1);
    }
    if (tid < 128) bias[tid] = b2[tid];
    if (tid < 4) rs[tid * 33 + 32] = -1;      // per-pair sentinel
    __syncthreads();

    const float2* A2 = (const float2*)Apre;
    const float2* B2 = (const float2*)Bpre;
    const uint2*  Bf2 = (const uint2*)Bfrag;

    for (int tile = blockIdx.x * 4 + pr; tile < N_PTILES; tile += gridDim.x * 4) {
        PBAR(pr);   // prev tile's msg/rs fully consumed (msg aliases As)
        int e0 = tile * 32;
        // ---- build A: warp w2 builds pair-local rows [16*w2, 16*w2+16)
        int base_e = e0 + w2 * 16;
        int s_l = g_srcs[base_e + (lane & 15)];
        int r_l = g_rcv[base_e + (lane & 15)];
        if (lane < 16) prs[w2 * 16 + lane] = r_l;
#pragma unroll
        for (int jb = 0; jb < 16; jb += 8) {
            float2 va[8], vb[8];
#pragma unroll
            for (int j = 0; j < 8; j++) {
                int s = __shfl_sync(0xffffffffu, s_l, jb + j);
                int r = __shfl_sync(0xffffffffu, r_l, jb + j);
                va[j] = A2[(size_t)r * 32 + lane];
                vb[j] = B2[(size_t)s * 32 + lane];
            }
#pragma unroll
            for (int j = 0; j < 8; j++) {
                __half2 h = __floats2half2_rn(fmaxf(va[j].x + vb[j].x, 0.f),
                                              fmaxf(va[j].y + vb[j].y, 0.f));
                As16[(w2 * 16 + jb + j) * 36 + lane] = h2bits(h);
            }
        }
        PBAR(pr);   // both warps' rows visible before cross-warp frag reads
        // ---- MMA: warp does pair rows [0,32) x cols [64*w2,+64)
        float d[2][8][4];
#pragma unroll
        for (int mt = 0; mt < 2; mt++)
#pragma unroll
            for (int nt = 0; nt < 8; nt++)
#pragma unroll
                for (int q = 0; q < 4; q++) d[mt][nt][q] = 0.f;
        const uint32_t* abase = As16 + (lane >> 2) * 36 + (lane & 3);
        for (int ks = 0; ks < 4; ks++) {
            uint32_t a[2][4];
#pragma unroll
            for (int mt = 0; mt < 2; mt++) {
                const uint32_t* ab = abase + mt * (16 * 36) + ks * 8;
                a[mt][0] = ab[0];
                a[mt][1] = ab[8 * 36];
                a[mt][2] = ab[4];
                a[mt][3] = ab[8 * 36 + 4];
            }
            const uint2* bp = Bf2 + ks * 32 + lane;
#pragma unroll
            for (int ntl = 0; ntl < 8; ntl++) {
                uint2 bb = bp[(w2 * 8 + ntl) * 128];
                mma_fp16(d[0][ntl], a[0], bb.x, bb.y);
                mma_fp16(d[1][ntl], a[1], bb.x, bb.y);
            }
        }
        PBAR(pr);   // pair done reading As before msg overwrites
        // ---- epilogue: relu(+bias) -> msg fp16x2 (pair rows, stride 66)
#pragma unroll
        for (int mt = 0; mt < 2; mt++) {
            int row = mt * 16 + (lane >> 2);
#pragma unroll
            for (int ntl = 0; ntl < 8; ntl++) {
                int col  = (w2 * 8 + ntl) * 8 + 2 * (lane & 3);
                int colh = col >> 1;
                float2 bv = *(float2*)&bias[col];
                msgh[row * 66 + colh] = __floats2half2_rn(
                    fmaxf(d[mt][ntl][0] + bv.x, 0.f),
                    fmaxf(d[mt][ntl][1] + bv.y, 0.f));
                msgh[(row + 8) * 66 + colh] = __floats2half2_rn(
                    fmaxf(d[mt][ntl][2] + bv.x, 0.f),
                    fmaxf(d[mt][ntl][3] + bv.y, 0.f));
            }
        }
        PBAR(pr);
        // ---- segmented reduce: 64 pair threads = 64 channel-pairs, 32 rows
        {
            int q = w2 * 32 + lane;    // channel pair: cols 2q, 2q+1
            float2 s = make_float2(0.f, 0.f);
            int rstart = 0;
            int cur = prs[0];
            for (int e = 0; e < 32; e++) {
                float2 v = __half22float2(msgh[e * 66 + q]);
                s.x += v.x; s.y += v.y;
                int nxt = prs[e + 1];     // prs[32] = -1 sentinel
                bool last = (e == 31) || (nxt != cur);
                if (last) {
                    float* dst = &g_accum[(size_t)cur * 128 + 2 * q];
                    if (rstart == 0 || e == 31) {
                        atomicAdd(dst, s.x);
                        atomicAdd(dst + 1, s.y);
                    } else {
                        *(float2*)dst = s;
                    }
                    s = make_float2(0.f, 0.f);
                    rstart = e + 1;
                    cur = nxt;
                }
            }
        }
    }
}

// ---------------- dense tail (mean folded in) ---------------------------------
__global__ __launch_bounds__(256) void tail_kernel(
    const float* __restrict__ h, const float* __restrict__ Wd1,
    const float* __restrict__ bd1, const float* __restrict__ Wd2,
    const float* __restrict__ bd2, float* __restrict__ out,
    const int* __restrict__ cnt) {
    __shared__ float Ws[128 * 64];
    int t = threadIdx.x;
    {
        const float4* src = (const float4*)Wd1;
        float4* dst = (float4*)Ws;
#pragma unroll
        for (int i = 0; i < 8; i++) dst[t + i * 256] = src[t + i * 256];
    }
    __syncthreads();
    int warp = t >> 5, lane = t & 31;
    int n = blockIdx.x * 8 + warp;
    if (n >= N_NODES) return;
    int c = cnt[n];
    float inv = (c > 0) ? 1.f / (float)c : 0.f;
    float x0 = h[(size_t)n * 128 + lane] * inv;
    float x1 = h[(size_t)n * 128 + 32 + lane] * inv;
    float x2 = h[(size_t)n * 128 + 64 + lane] * inv;
    float x3 = h[(size_t)n * 128 + 96 + lane] * inv;
    float g0 = bd1[lane], g1 = bd1[lane + 32];
#pragma unroll
    for (int kk = 0; kk < 32; kk++) {
        float xk;
        xk = __shfl_sync(0xffffffffu, x0, kk);
        g0 = fmaf(xk, Ws[kk * 64 + lane], g0);
        g1 = fmaf(xk, Ws[kk * 64 + lane + 32], g1);
        xk = __shfl_sync(0xffffffffu, x1, kk);
        g0 = fmaf(xk, Ws[(kk + 32) * 64 + lane], g0);
        g1 = fmaf(xk, Ws[(kk + 32) * 64 + lane + 32], g1);
        xk = __shfl_sync(0xffffffffu, x2, kk);
        g0 = fmaf(xk, Ws[(kk + 64) * 64 + lane], g0);
        g1 = fmaf(xk, Ws[(kk + 64) * 64 + lane + 32], g1);
        xk = __shfl_sync(0xffffffffu, x3, kk);
        g0 = fmaf(xk, Ws[(kk + 96) * 64 + lane], g0);
        g1 = fmaf(xk, Ws[(kk + 96) * 64 + lane + 32], g1);
    }
    g0 = fmaxf(g0, 0.f);
    g1 = fmaxf(g1, 0.f);
    float p = g0 * Wd2[lane] + g1 * Wd2[lane + 32];
#pragma unroll
    for (int o = 16; o > 0; o >>= 1) p += __shfl_xor_sync(0xffffffffu, p, o);
    if (lane == 0) out[n] = p + bd2[0];
}

// ---------------- launch ------------------------------------------------------
extern "C" void kernel_launch(void* const* d_in, const int* in_sizes, int n_in,
                              void* d_out, int out_size) {
    const float* x         = (const float*)d_in[0];
    const int*   senders   = (const int*)d_in[1];
    const int*   receivers = (const int*)d_in[2];
    const float* W1a = (const float*)d_in[3];
    const float* b1a = (const float*)d_in[4];
    const float* W2a = (const float*)d_in[5];
    const float* b2a = (const float*)d_in[6];
    const float* W1b = (const float*)d_in[7];
    const float* b1b = (const float*)d_in[8];
    const float* W2b = (const float*)d_in[9];
    const float* b2b = (const float*)d_in[10];
    const float* Wd1 = (const float*)d_in[11];
    const float* bd1 = (const float*)d_in[12];
    const float* Wd2 = (const float*)d_in[13];
    const float* bd2 = (const float*)d_in[14];
    float* out = (float*)d_out;

    static float* pA = nullptr;
    static float* pB = nullptr;
    static float* pAcc = nullptr;
    static int*   pCnt = nullptr;
    static int    nSM = 148;
    if (!pA) {
        cudaGetSymbolAddress((void**)&pA, g_A);
        cudaGetSymbolAddress((void**)&pB, g_B);
        cudaGetSymbolAddress((void**)&pAcc, g_accum);
        cudaGetSymbolAddress((void**)&pCnt, g_cnt);
        cudaFuncSetAttribute(edge_mma_kernel,
                             cudaFuncAttributeMaxDynamicSharedMemorySize,
                             SM_TOTAL);
        cudaDeviceProp prop;
        if (cudaGetDeviceProperties(&prop, 0) == cudaSuccess)
            nSM = prop.multiProcessorCount;
    }

    // Single linear stream (R15: cross-stream fork/join costs ~190 us here).
    node_ab_kernel<<<N_NODES / 16, 128>>>(x, W1a, b1a, pA, pB, nullptr, nullptr);
    zero_kernel<<<(N_NODES * 32 + 255) / 256, 256>>>();
    hist_kernel<<<(N_EDGES + 255) / 256, 256>>>(receivers);
    blocksum_kernel<<<SCAN_BLOCKS, 1024>>>();
    bsum_scan_kernel<<<1, 32>>>();
    scan_out_kernel<<<SCAN_BLOCKS, 1024>>>();
    fill_kernel<<<(N_EDGES + 255) / 256, 256>>>(senders, receivers);

    int mmaBlocks = 3 * nSM;

    // Layer 1
    edge_mma_kernel<<<mmaBlocks, 256, SM_TOTAL>>>(pA, pB, W2a, b2a);
    // Layer 2 (mean folded into the accum read; accum re-zeroed in-kernel)
    node_ab_kernel<<<N_NODES / 16, 128>>>(pAcc, W1b, b1b, pA, pB, pCnt, pAcc);
    edge_mma_kernel<<<mmaBlocks, 256, SM_TOTAL>>>(pA, pB, W2b, b2b);
    // Dense tail (mean of layer-2 folded in)
    tail_kernel<<<(N_NODES + 7) / 8, 256>>>(pAcc, Wd1, bd1, Wd2, bd2, out, pCnt);
}